// round 11
// baseline (speedup 1.0000x reference)
#include <cuda_runtime.h>

// MLP_RSNA6: out[b, v[g,t]] = relu(sum_i x[b, k[g,i]] * w1[i] + b1) * w2[t] + b2[t]
// B=500000, TOTAL_IN=200, GROUPS=25, IN_NUM=8, OUT=75.
//
// Dataset property (verified at runtime): k = arange(200).reshape(25,8) and
// v = arange(75).reshape(25,3) (identity gather/scatter). Then task
// t = row*25+g reads x4[2t], x4[2t+1] (32 contiguous bytes) and writes
// out[3t..3t+2] (12 contiguous bytes) -> fully coalesced, no smem, no
// barriers. General index-following fallback kept for any indices.
//
// R11: persistent-grid variant of the proven R4 schedule. grid = 592
// (148 SMs x 4 resident blocks) -> exactly one wave, no wave-quantization
// tail, no wave transitions. Loop body identical to R4 (4-task batches,
// front-batched 8x LDG.128 per thread, streaming ld/st hints).

#define TPB 256
#define RESIDENT_BLOCKS 592   // 148 SMs * 4 blocks/SM @ ~58 regs
#define NGROUPS 25
#define IN_NUM  8
#define NCOLS   200
#define NOUT    75

__global__ __launch_bounds__(TPB)
void mlp_rsna6_fused(const float* __restrict__ x,
                     const float* __restrict__ w1,
                     const float* __restrict__ b1,
                     const float* __restrict__ w2,
                     const float* __restrict__ b2,
                     const int* __restrict__ kidx,
                     const int* __restrict__ vidx,
                     float* __restrict__ out,
                     int B)
{
    // ---- runtime identity-permutation check (block-local, cheap) ----
    __shared__ int s_ok;
    if (threadIdx.x == 0) s_ok = 1;
    __syncthreads();
    {
        bool bad = false;
        for (int e = threadIdx.x; e < NGROUPS * IN_NUM; e += TPB)
            bad |= (__ldg(&kidx[e]) != e);
        for (int e = threadIdx.x; e < NGROUPS * 3; e += TPB)
            bad |= (__ldg(&vidx[e]) != e);
        if (bad) s_ok = 0;
    }
    __syncthreads();

    // ---- weights to registers (broadcast, L1-resident) ----
    float w1r[IN_NUM];
#pragma unroll
    for (int i = 0; i < IN_NUM; i++) w1r[i] = __ldg(&w1[i]);
    const float b1r = __ldg(&b1[0]);
    float w2r[3], b2r[3];
#pragma unroll
    for (int t = 0; t < 3; t++) { w2r[t] = __ldg(&w2[t]); b2r[t] = __ldg(&b2[t]); }

    if (s_ok) {
        // ================= FAST PATH (identity indices) =================
        // task t in [0, B*25): reads x4[2t], x4[2t+1] (32B contiguous/lane),
        // writes out[3t..3t+2] (12B contiguous/lane).
        const float4* x4 = reinterpret_cast<const float4*>(x);
        const int NT = B * NGROUPS;
        const int stride = gridDim.x * TPB;
        int base = blockIdx.x * TPB + threadIdx.x;

        for (; base < NT; base += 4 * stride) {
            float4 a0[4], a1[4];
            int tt[4];
#pragma unroll
            for (int j = 0; j < 4; j++) {
                int t = base + j * stride;
                tt[j] = t;
                if (t < NT) {
                    a0[j] = __ldcs(&x4[2 * t]);
                    a1[j] = __ldcs(&x4[2 * t + 1]);
                }
            }
#pragma unroll
            for (int j = 0; j < 4; j++) {
                int t = tt[j];
                if (t < NT) {
                    float h = b1r;
                    h = fmaf(a0[j].x, w1r[0], h);
                    h = fmaf(a0[j].y, w1r[1], h);
                    h = fmaf(a0[j].z, w1r[2], h);
                    h = fmaf(a0[j].w, w1r[3], h);
                    h = fmaf(a1[j].x, w1r[4], h);
                    h = fmaf(a1[j].y, w1r[5], h);
                    h = fmaf(a1[j].z, w1r[6], h);
                    h = fmaf(a1[j].w, w1r[7], h);
                    h = fmaxf(h, 0.0f);
                    __stcs(&out[3 * t + 0], fmaf(h, w2r[0], b2r[0]));
                    __stcs(&out[3 * t + 1], fmaf(h, w2r[1], b2r[1]));
                    __stcs(&out[3 * t + 2], fmaf(h, w2r[2], b2r[2]));
                }
            }
        }
    } else {
        // ============ GENERAL FALLBACK (arbitrary indices) ============
        const int stride = gridDim.x * TPB;
        for (int r = blockIdx.x * TPB + threadIdx.x; r < B; r += stride) {
            const float* xr = x + (long long)r * NCOLS;
            float* orow = out + (long long)r * NOUT;
#pragma unroll 5
            for (int j = 0; j < NOUT; j++) orow[j] = 0.0f;
#pragma unroll 1
            for (int g = 0; g < NGROUPS; g++) {
                float h = b1r;
#pragma unroll
                for (int i = 0; i < IN_NUM; i++)
                    h = fmaf(__ldg(&xr[__ldg(&kidx[g * IN_NUM + i])]), w1r[i], h);
                h = fmaxf(h, 0.0f);
#pragma unroll
                for (int t = 0; t < 3; t++)
                    orow[__ldg(&vidx[g * 3 + t])] = fmaf(h, w2r[t], b2r[t]);
            }
        }
    }
}

extern "C" void kernel_launch(void* const* d_in, const int* in_sizes, int n_in,
                              void* d_out, int out_size)
{
    const float* x    = (const float*)d_in[0];
    const float* w1   = (const float*)d_in[1];
    const float* b1   = (const float*)d_in[2];
    const float* w2   = (const float*)d_in[3];
    const float* b2   = (const float*)d_in[4];
    const int*   kidx = (const int*)d_in[5];
    const int*   vidx = (const int*)d_in[6];
    float* out = (float*)d_out;

    const int B  = in_sizes[0] / NCOLS;
    const long long NT = (long long)B * NGROUPS;

    // persistent single-wave grid; never exceed what the work needs
    long long need = (NT + (long long)TPB * 4 - 1) / ((long long)TPB * 4);
    int grid = (int)(need < RESIDENT_BLOCKS ? need : RESIDENT_BLOCKS);
    if (grid < 1) grid = 1;

    mlp_rsna6_fused<<<grid, TPB>>>(x, w1, b1, w2, b2, kidx, vidx, out, B);
}

// round 12
// speedup vs baseline: 1.0397x; 1.0397x over previous
#include <cuda_runtime.h>

// MLP_RSNA6: out[b, v[g,t]] = relu(sum_i x[b, k[g,i]] * w1[i] + b1) * w2[t] + b2[t]
// B=500000, TOTAL_IN=200, GROUPS=25, IN_NUM=8, OUT=75.
//
// Dataset property (verified at runtime): k = arange(200).reshape(25,8) and
// v = arange(75).reshape(25,3) (identity gather/scatter). Then task
// t = row*25+g reads x4[2t], x4[2t+1] (32 contiguous bytes) and writes
// out[3t..3t+2] (12 contiguous bytes) -> fully coalesced, no smem, no
// barriers. Verified at runtime from the index tensors; general
// index-following fallback kept for correctness on any indices.
//
// FINAL — converged at the HBM roofline. Measured landscape:
//   R4  (this schedule)           81.4us  DRAM 85.4%   <- best
//   R5  +occupancy                82.0us  84.7%  (occupancy not binding)
//   R6  warp-contiguous loads     82.0us  83.6%  (L1 not binding)
//   R8  software pipeline         84.0us  77.5%  (MLP per thread dropped)
//   R11 persistent 1-wave grid    84.7us  78.1%  (lost wave-overlap slack)
// Traffic = 550 MB compulsory minimum in all variants; binding constraint is
// the DRAM pipe at ~85% of 8 TB/s (practical mixed-stream ceiling).
// Schedule: grid-stride, 4-task batches, interleaved load arrays so ptxas
// front-batches 8x LDG.128/thread (MLP=8, regs=58), streaming ld/st hints,
// ~10-wave oversubscribed grid for transition overlap / load balance.

#define TPB 256
#define NGROUPS 25
#define IN_NUM  8
#define NCOLS   200
#define NOUT    75

__global__ __launch_bounds__(TPB)
void mlp_rsna6_fused(const float* __restrict__ x,
                     const float* __restrict__ w1,
                     const float* __restrict__ b1,
                     const float* __restrict__ w2,
                     const float* __restrict__ b2,
                     const int* __restrict__ kidx,
                     const int* __restrict__ vidx,
                     float* __restrict__ out,
                     int B)
{
    // ---- runtime identity-permutation check (block-local, cheap) ----
    __shared__ int s_ok;
    if (threadIdx.x == 0) s_ok = 1;
    __syncthreads();
    {
        bool bad = false;
        for (int e = threadIdx.x; e < NGROUPS * IN_NUM; e += TPB)
            bad |= (__ldg(&kidx[e]) != e);
        for (int e = threadIdx.x; e < NGROUPS * 3; e += TPB)
            bad |= (__ldg(&vidx[e]) != e);
        if (bad) s_ok = 0;
    }
    __syncthreads();

    // ---- weights to registers (broadcast, L1-resident) ----
    float w1r[IN_NUM];
#pragma unroll
    for (int i = 0; i < IN_NUM; i++) w1r[i] = __ldg(&w1[i]);
    const float b1r = __ldg(&b1[0]);
    float w2r[3], b2r[3];
#pragma unroll
    for (int t = 0; t < 3; t++) { w2r[t] = __ldg(&w2[t]); b2r[t] = __ldg(&b2[t]); }

    if (s_ok) {
        // ================= FAST PATH (identity indices) =================
        // task t in [0, B*25): row = t/25, g = t%25.
        // reads  x4[2t], x4[2t+1]  (32B contiguous per lane)
        // writes out[3t .. 3t+2]   (12B contiguous per lane)
        const float4* x4 = reinterpret_cast<const float4*>(x);
        const int NT = B * NGROUPS;
        const int stride = gridDim.x * TPB;
        int base = blockIdx.x * TPB + threadIdx.x;

        for (; base < NT; base += 4 * stride) {
            float4 a0[4], a1[4];
            int tt[4];
#pragma unroll
            for (int j = 0; j < 4; j++) {
                int t = base + j * stride;
                tt[j] = t;
                if (t < NT) {
                    a0[j] = __ldcs(&x4[2 * t]);
                    a1[j] = __ldcs(&x4[2 * t + 1]);
                }
            }
#pragma unroll
            for (int j = 0; j < 4; j++) {
                int t = tt[j];
                if (t < NT) {
                    float h = b1r;
                    h = fmaf(a0[j].x, w1r[0], h);
                    h = fmaf(a0[j].y, w1r[1], h);
                    h = fmaf(a0[j].z, w1r[2], h);
                    h = fmaf(a0[j].w, w1r[3], h);
                    h = fmaf(a1[j].x, w1r[4], h);
                    h = fmaf(a1[j].y, w1r[5], h);
                    h = fmaf(a1[j].z, w1r[6], h);
                    h = fmaf(a1[j].w, w1r[7], h);
                    h = fmaxf(h, 0.0f);
                    __stcs(&out[3 * t + 0], fmaf(h, w2r[0], b2r[0]));
                    __stcs(&out[3 * t + 1], fmaf(h, w2r[1], b2r[1]));
                    __stcs(&out[3 * t + 2], fmaf(h, w2r[2], b2r[2]));
                }
            }
        }
    } else {
        // ============ GENERAL FALLBACK (arbitrary indices) ============
        // Thread per row, direct (strided) loads. Correct for any k/v.
        const int stride = gridDim.x * TPB;
        for (int r = blockIdx.x * TPB + threadIdx.x; r < B; r += stride) {
            const float* xr = x + (long long)r * NCOLS;
            float* orow = out + (long long)r * NOUT;
            // reference initializes out to zeros before scatter
#pragma unroll 5
            for (int j = 0; j < NOUT; j++) orow[j] = 0.0f;
#pragma unroll 1
            for (int g = 0; g < NGROUPS; g++) {
                float h = b1r;
#pragma unroll
                for (int i = 0; i < IN_NUM; i++)
                    h = fmaf(__ldg(&xr[__ldg(&kidx[g * IN_NUM + i])]), w1r[i], h);
                h = fmaxf(h, 0.0f);
#pragma unroll
                for (int t = 0; t < 3; t++)
                    orow[__ldg(&vidx[g * 3 + t])] = fmaf(h, w2r[t], b2r[t]);
            }
        }
    }
}

extern "C" void kernel_launch(void* const* d_in, const int* in_sizes, int n_in,
                              void* d_out, int out_size)
{
    const float* x    = (const float*)d_in[0];
    const float* w1   = (const float*)d_in[1];
    const float* b1   = (const float*)d_in[2];
    const float* w2   = (const float*)d_in[3];
    const float* b2   = (const float*)d_in[4];
    const int*   kidx = (const int*)d_in[5];
    const int*   vidx = (const int*)d_in[6];
    float* out = (float*)d_out;

    const int B  = in_sizes[0] / NCOLS;
    const long long NT = (long long)B * NGROUPS;
    // ~8 tasks per thread (grid 6104 @ B=500000): best-measured schedule
    int grid = (int)((NT + (long long)TPB * 8 - 1) / ((long long)TPB * 8));
    if (grid < 1) grid = 1;

    mlp_rsna6_fused<<<grid, TPB>>>(x, w1, b1, w2, b2, kidx, vidx, out, B);
}